// round 10
// baseline (speedup 1.0000x reference)
#include <cuda_runtime.h>

typedef unsigned long long u64;
typedef unsigned int u32;

// ---------------- packed f32x2 / f16x2 helpers (sm_10x) ----------------
__device__ __forceinline__ u64 ffma2(u64 a, u64 b, u64 c) {
    u64 d;
    asm("fma.rn.f32x2 %0, %1, %2, %3;" : "=l"(d) : "l"(a), "l"(b), "l"(c));
    return d;
}
__device__ __forceinline__ u64 mul2(u64 a, u64 b) {
    u64 d;
    asm("mul.rn.f32x2 %0, %1, %2;" : "=l"(d) : "l"(a), "l"(b));
    return d;
}
__device__ __forceinline__ u64 pack2(float lo, float hi) {
    u64 r;
    asm("mov.b64 %0, {%1, %2};" : "=l"(r) : "f"(lo), "f"(hi));
    return r;
}
__device__ __forceinline__ void unpack2(u64 v, float& lo, float& hi) {
    asm("mov.b64 {%0, %1}, %2;" : "=f"(lo), "=f"(hi) : "l"(v));
}
__device__ __forceinline__ float tanh_ap(float x) {
    float y;
    asm("tanh.approx.f32 %0, %1;" : "=f"(y) : "f"(x));
    return y;
}
__device__ __forceinline__ float ex2_ap(float x) {
    float y;
    asm("ex2.approx.f32 %0, %1;" : "=f"(y) : "f"(x));
    return y;
}
__device__ __forceinline__ float lg2_ap(float x) {
    float y;
    asm("lg2.approx.f32 %0, %1;" : "=f"(y) : "f"(x));
    return y;
}
__device__ __forceinline__ u64 tanh2(u64 v) {
    float lo, hi;
    unpack2(v, lo, hi);
    return pack2(tanh_ap(lo), tanh_ap(hi));
}
// fp16x2 ops (HFMA2 path: 32-bit regs -> rt2 instead of FFMA2's 3-even-bank rt3)
__device__ __forceinline__ u32 hfma2(u32 a, u32 b, u32 c) {
    u32 d;
    asm("fma.rn.f16x2 %0, %1, %2, %3;" : "=r"(d) : "r"(a), "r"(b), "r"(c));
    return d;
}
__device__ __forceinline__ u32 tanh_h2(u32 v) {
    u32 d;
    asm("tanh.approx.f16x2 %0, %1;" : "=r"(d) : "r"(v));
    return d;
}
__device__ __forceinline__ u32 f32x2_to_h2(u64 v) {
    u32 d;
    asm("{\n\t.reg .f32 lo, hi;\n\tmov.b64 {lo, hi}, %1;\n\t"
        "cvt.rn.f16x2.f32 %0, hi, lo;\n\t}" : "=r"(d) : "l"(v));
    return d;
}
__device__ __forceinline__ u64 h2_to_f32x2(u32 v) {
    u64 d;
    asm("{\n\t.reg .b16 l, h;\n\t.reg .f32 flo, fhi;\n\tmov.b32 {l, h}, %1;\n\t"
        "cvt.f32.f16 flo, l;\n\tcvt.f32.f16 fhi, h;\n\tmov.b64 %0, {flo, fhi};\n\t}"
        : "=l"(d) : "r"(v));
    return d;
}

// ---------------- constant tables ----------------
// f32x2 (u64, duplicated (w,w)) for layers 1,3,4,5,head + tail.
// f16x2 (u32, duplicated (w,w)) for layer 2 (HFMA2 path).
// Scalar compile-time indices only -> LDCU.
enum {
    O_W1 = 0,           // 16x8  = 128
    O_B1 = 128,         // 16
    O_W3 = 144,         // 12x16 = 192
    O_B3 = 336,         // 12
    O_W4 = 348,         // 8x12  = 96
    O_B4 = 444,         // 8
    O_W5 = 452,         // 4x8   = 32
    O_B5 = 484,         // 4
    O_WH = 488,         // 4x4   = 16
    O_BH = 504,         // 4
    W_TOTAL = 508
};
enum { D_TOTAL = 21 };  // D[0..17]=Wf dup, D[18]=bf0, D[19]=bf1, D[20]=-gamma*log2e

struct CParams {
    u64 W[W_TOTAL];
    u64 D[D_TOTAL];
    u32 HW2[256];       // layer2 weights, f16x2 (w,w)
    u32 HB2[16];        // layer2 bias,    f16x2 (b,b)
};

__constant__ CParams cP;
__device__ CParams gScratch;

#define LOG2E 1.4426950408889634f
#define LN2   0.6931471805599453f

// ---------------- prep kernel ----------------
__global__ void prep_kernel(
    const float* __restrict__ W1, const float* __restrict__ b1,
    const float* __restrict__ W2, const float* __restrict__ b2,
    const float* __restrict__ W3, const float* __restrict__ b3,
    const float* __restrict__ W4, const float* __restrict__ b4,
    const float* __restrict__ W5, const float* __restrict__ b5,
    const float* __restrict__ Wh, const float* __restrict__ bh,
    const float* __restrict__ Wf, const float* __restrict__ bf,
    const float* __restrict__ gamma)
{
    int tid = threadIdx.x;
#define CP_(off, src, n)                                       \
    for (int i = tid; i < (n); i += blockDim.x) {              \
        float f = (src)[i];                                    \
        gScratch.W[(off) + i] = pack2(f, f);                   \
    }
    CP_(O_W1, W1, 128); CP_(O_B1, b1, 16);
    CP_(O_W3, W3, 192); CP_(O_B3, b3, 12);
    CP_(O_W4, W4, 96);  CP_(O_B4, b4, 8);
    CP_(O_W5, W5, 32);  CP_(O_B5, b5, 4);
    CP_(O_WH, Wh, 16);  CP_(O_BH, bh, 4);
#undef CP_
    // layer 2 -> f16x2 duplicated
    for (int i = tid; i < 256; i += blockDim.x) {
        float f = W2[i];
        u32 h;
        asm("cvt.rn.f16x2.f32 %0, %1, %1;" : "=r"(h) : "f"(f));
        gScratch.HW2[i] = h;
    }
    for (int i = tid; i < 16; i += blockDim.x) {
        float f = b2[i];
        u32 h;
        asm("cvt.rn.f16x2.f32 %0, %1, %1;" : "=r"(h) : "f"(f));
        gScratch.HB2[i] = h;
    }
    if (tid < 18) { float f = Wf[tid]; gScratch.D[tid] = pack2(f, f); }
    if (tid == 18) { float f = bf[0]; gScratch.D[18] = pack2(f, f); }
    if (tid == 19) { float f = bf[1]; gScratch.D[19] = pack2(f, f); }
    if (tid == 20) { float f = -gamma[0] * LOG2E; gScratch.D[20] = pack2(f, f); }
}

// ---------------- f32x2 dense layer on one packed pair ----------------
template <int OFF_W, int OFF_B, int IN, int OUT, bool ACT>
__device__ __forceinline__ void layerfn(const u64* __restrict__ in, u64* __restrict__ out) {
#pragma unroll
    for (int j = 0; j < OUT; j++) {
        u64 a = cP.W[OFF_B + j];
#pragma unroll
        for (int i = 0; i < IN; i++) {
            a = ffma2(in[i], cP.W[OFF_W + j * IN + i], a);
        }
        if (ACT) a = tanh2(a);
        out[j] = a;
    }
}

__device__ __forceinline__ void lsm2(float a, float b, float& ra, float& rb) {
    float m  = fmaxf(a, b);
    float mn = fminf(a, b);
    float lse = m + lg2_ap(1.0f + ex2_ap((mn - m) * LOG2E)) * LN2;
    ra = a - lse; rb = b - lse;
}

// ---------------- persistent main kernel: grid-stride over sample pairs ----------------
__global__ __launch_bounds__(128, 3) void qcnn_kernel(
    const float* __restrict__ x, float* __restrict__ out, int nb)
{
    const int stride = gridDim.x * blockDim.x;
    const int npairs = (nb + 1) >> 1;
    for (int p = blockIdx.x * blockDim.x + threadIdx.x; p < npairs; p += stride) {
        int base = p * 2;
        const bool full = (base + 2 <= nb);

        // ---- load 2 samples ----
        u64 A[16], B[16];
        {
            int i1 = full ? base + 1 : nb - 1;
            const float4* p0 = (const float4*)(x + (size_t)base * 8);
            const float4* p1 = (const float4*)(x + (size_t)i1 * 8);
            float4 a = p0[0], b = p0[1];
            float4 c = p1[0], d = p1[1];
            A[0] = pack2(a.x, c.x); A[1] = pack2(a.y, c.y);
            A[2] = pack2(a.z, c.z); A[3] = pack2(a.w, c.w);
            A[4] = pack2(b.x, d.x); A[5] = pack2(b.y, d.y);
            A[6] = pack2(b.z, d.z); A[7] = pack2(b.w, d.w);
        }

        // L1 (f32x2): 8 -> 16
        layerfn<O_W1, O_B1, 8, 16, true>(A, B);

        // L2 (f16x2 / HFMA2): 16 -> 16
        {
            u32 H[16];
#pragma unroll
            for (int i = 0; i < 16; i++) H[i] = f32x2_to_h2(B[i]);
#pragma unroll
            for (int j = 0; j < 16; j++) {
                u32 acc = cP.HB2[j];
#pragma unroll
                for (int i = 0; i < 16; i++) {
                    acc = hfma2(H[i], cP.HW2[j * 16 + i], acc);
                }
                acc = tanh_h2(acc);
                A[j] = h2_to_f32x2(acc);
            }
        }

        // L3..head (f32x2)
        layerfn<O_W3, O_B3, 16, 12, true >(A, B);
        layerfn<O_W4, O_B4, 12, 8,  true >(B, A);
        layerfn<O_W5, O_B5, 8,  4,  true >(A, B);
        layerfn<O_WH, O_BH, 4,  4,  false>(B, A);   // cls_out (pair) in A[0..3]

        // ---- packed tail: RBF + final linear ----
        u64 s2 = mul2(A[0], A[0]);
        s2 = ffma2(A[1], A[1], s2);
        s2 = ffma2(A[2], A[2], s2);
        s2 = ffma2(A[3], A[3], s2);
        u64 g = mul2(s2, cP.D[20]);
        float glo, ghi;
        unpack2(g, glo, ghi);
        u64 k = pack2(ex2_ap(glo), ex2_ap(ghi));
        u64 o0 = cP.D[18];
        o0 = ffma2(A[0], cP.D[0], o0);
        o0 = ffma2(A[1], cP.D[1], o0);
        o0 = ffma2(A[2], cP.D[2], o0);
        o0 = ffma2(A[3], cP.D[3], o0);
        o0 = ffma2(k,    cP.D[8], o0);
        u64 o1 = cP.D[19];
        o1 = ffma2(A[0], cP.D[9],  o1);
        o1 = ffma2(A[1], cP.D[10], o1);
        o1 = ffma2(A[2], cP.D[11], o1);
        o1 = ffma2(A[3], cP.D[12], o1);
        o1 = ffma2(k,    cP.D[17], o1);

        float l0a, l0b, l1a, l1b;
        unpack2(o0, l0a, l0b);   // sample0 / sample1 logit0
        unpack2(o1, l1a, l1b);   // sample0 / sample1 logit1
        float r0a, r0b, r1a, r1b;
        lsm2(l0a, l1a, r0a, r0b);
        lsm2(l0b, l1b, r1a, r1b);

        if (full) {
            *(float4*)(out + (size_t)base * 2) = make_float4(r0a, r0b, r1a, r1b);
        } else {
            out[base * 2]     = r0a;
            out[base * 2 + 1] = r0b;
        }
    }
}

extern "C" void kernel_launch(void* const* d_in, const int* in_sizes, int n_in,
                              void* d_out, int out_size) {
    const float* x  = (const float*)d_in[0];
    const float* W1 = (const float*)d_in[1];
    const float* b1 = (const float*)d_in[2];
    const float* W2 = (const float*)d_in[3];
    const float* b2 = (const float*)d_in[4];
    const float* W3 = (const float*)d_in[5];
    const float* b3 = (const float*)d_in[6];
    const float* W4 = (const float*)d_in[7];
    const float* b4 = (const float*)d_in[8];
    const float* W5 = (const float*)d_in[9];
    const float* b5 = (const float*)d_in[10];
    const float* Wh = (const float*)d_in[11];
    const float* bh = (const float*)d_in[12];
    const float* Wf = (const float*)d_in[13];
    const float* bf = (const float*)d_in[14];
    const float* gm = (const float*)d_in[15];

    // 1) build duplicated weight tables in device scratch
    prep_kernel<<<1, 256>>>(W1, b1, W2, b2, W3, b3, W4, b4, W5, b5,
                            Wh, bh, Wf, bf, gm);

    // 2) move into the constant bank (D2D async copy — graph-capturable)
    void* scratch_addr = nullptr;
    cudaGetSymbolAddress(&scratch_addr, gScratch);
    cudaMemcpyToSymbolAsync(cP, scratch_addr, sizeof(CParams), 0,
                            cudaMemcpyDeviceToDevice, 0);

    // 3) persistent main kernel: 3 CTAs/SM x 148 SMs
    int nb = in_sizes[0] / 8;
    int npairs = (nb + 1) / 2;
    int threads = 128;
    int blocks = 148 * 3;
    int needed = (npairs + threads - 1) / threads;
    if (blocks > needed) blocks = needed;
    qcnn_kernel<<<blocks, threads>>>(x, (float*)d_out, nb);
}

// round 11
// speedup vs baseline: 1.0886x; 1.0886x over previous
#include <cuda_runtime.h>

typedef unsigned long long u64;

// ---------------- packed f32x2 helpers (sm_10x) ----------------
__device__ __forceinline__ u64 ffma2(u64 a, u64 b, u64 c) {
    u64 d;
    asm("fma.rn.f32x2 %0, %1, %2, %3;" : "=l"(d) : "l"(a), "l"(b), "l"(c));
    return d;
}
__device__ __forceinline__ u64 mul2(u64 a, u64 b) {
    u64 d;
    asm("mul.rn.f32x2 %0, %1, %2;" : "=l"(d) : "l"(a), "l"(b));
    return d;
}
__device__ __forceinline__ u64 pack2(float lo, float hi) {
    u64 r;
    asm("mov.b64 %0, {%1, %2};" : "=l"(r) : "f"(lo), "f"(hi));
    return r;
}
__device__ __forceinline__ void unpack2(u64 v, float& lo, float& hi) {
    asm("mov.b64 {%0, %1}, %2;" : "=f"(lo), "=f"(hi) : "l"(v));
}
__device__ __forceinline__ float tanh_ap(float x) {
    float y;
    asm("tanh.approx.f32 %0, %1;" : "=f"(y) : "f"(x));
    return y;
}
__device__ __forceinline__ float ex2_ap(float x) {
    float y;
    asm("ex2.approx.f32 %0, %1;" : "=f"(y) : "f"(x));
    return y;
}
__device__ __forceinline__ float lg2_ap(float x) {
    float y;
    asm("lg2.approx.f32 %0, %1;" : "=f"(y) : "f"(x));
    return y;
}
__device__ __forceinline__ u64 tanh2(u64 v) {
    float lo, hi;
    unpack2(v, lo, hi);
    return pack2(tanh_ap(lo), tanh_ap(hi));
}

// ---------------- constant weight table (u64 units, weights duplicated (w,w)) ----------------
// ALL weights from the constant bank, scalar compile-time indices only (LDCU).
// (R4: vector LDC regressed; R7: smem split regressed; R8: reg-cap-72 regressed;
//  R10: fp16 layer + cvt overhead regressed.)
enum {
    O_W1 = 0,           // 16x8  = 128
    O_B1 = 128,         // 16
    O_W2 = 144,         // 16x16 = 256
    O_B2 = 400,         // 16
    O_W3 = 416,         // 12x16 = 192
    O_B3 = 608,         // 12
    O_W4 = 620,         // 8x12  = 96
    O_B4 = 716,         // 8
    O_W5 = 724,         // 4x8   = 32
    O_B5 = 756,         // 4
    O_WH = 760,         // 4x4   = 16
    O_BH = 776,         // 4
    W_TOTAL = 780
};
enum { D_TOTAL = 21 };  // D[0..17]=Wf dup, D[18]=bf0, D[19]=bf1, D[20]=-gamma*log2e

struct CParams {
    u64 W[W_TOTAL];
    u64 D[D_TOTAL];
};

__constant__ CParams cP;
__device__ CParams gScratch;

#define LOG2E 1.4426950408889634f
#define LN2   0.6931471805599453f

// ---------------- prep kernel ----------------
__global__ void prep_kernel(
    const float* __restrict__ W1, const float* __restrict__ b1,
    const float* __restrict__ W2, const float* __restrict__ b2,
    const float* __restrict__ W3, const float* __restrict__ b3,
    const float* __restrict__ W4, const float* __restrict__ b4,
    const float* __restrict__ W5, const float* __restrict__ b5,
    const float* __restrict__ Wh, const float* __restrict__ bh,
    const float* __restrict__ Wf, const float* __restrict__ bf,
    const float* __restrict__ gamma)
{
    int tid = threadIdx.x;
#define CP_(off, src, n)                                       \
    for (int i = tid; i < (n); i += blockDim.x) {              \
        float f = (src)[i];                                    \
        gScratch.W[(off) + i] = pack2(f, f);                   \
    }
    CP_(O_W1, W1, 128); CP_(O_B1, b1, 16);
    CP_(O_W2, W2, 256); CP_(O_B2, b2, 16);
    CP_(O_W3, W3, 192); CP_(O_B3, b3, 12);
    CP_(O_W4, W4, 96);  CP_(O_B4, b4, 8);
    CP_(O_W5, W5, 32);  CP_(O_B5, b5, 4);
    CP_(O_WH, Wh, 16);  CP_(O_BH, bh, 4);
#undef CP_
    if (tid < 18) { float f = Wf[tid]; gScratch.D[tid] = pack2(f, f); }
    if (tid == 18) { float f = bf[0]; gScratch.D[18] = pack2(f, f); }
    if (tid == 19) { float f = bf[1]; gScratch.D[19] = pack2(f, f); }
    if (tid == 20) { float f = -gamma[0] * LOG2E; gScratch.D[20] = pack2(f, f); }
}

// ---------------- dense layer on TWO packed pairs (4 samples) ----------------
template <int OFF_W, int OFF_B, int IN, int OUT, bool ACT>
__device__ __forceinline__ void layerfn(const u64* __restrict__ in0, const u64* __restrict__ in1,
                                        u64* __restrict__ out0, u64* __restrict__ out1) {
#pragma unroll
    for (int j = 0; j < OUT; j++) {
        u64 a0 = cP.W[OFF_B + j];
        u64 a1 = a0;
#pragma unroll
        for (int i = 0; i < IN; i++) {
            u64 w = cP.W[OFF_W + j * IN + i];
            a0 = ffma2(in0[i], w, a0);
            a1 = ffma2(in1[i], w, a1);
        }
        if (ACT) { a0 = tanh2(a0); a1 = tanh2(a1); }
        out0[j] = a0;
        out1[j] = a1;
    }
}

// Packed tail for one pair-group: RBF + final linear -> packed logits.
__device__ __forceinline__ void tail_pair(const u64* __restrict__ A, u64& o0, u64& o1) {
    u64 s2 = mul2(A[0], A[0]);
    s2 = ffma2(A[1], A[1], s2);
    s2 = ffma2(A[2], A[2], s2);
    s2 = ffma2(A[3], A[3], s2);
    u64 g = mul2(s2, cP.D[20]);
    float glo, ghi;
    unpack2(g, glo, ghi);
    u64 k = pack2(ex2_ap(glo), ex2_ap(ghi));
    o0 = cP.D[18];
    o0 = ffma2(A[0], cP.D[0], o0);
    o0 = ffma2(A[1], cP.D[1], o0);
    o0 = ffma2(A[2], cP.D[2], o0);
    o0 = ffma2(A[3], cP.D[3], o0);
    o0 = ffma2(k,    cP.D[8], o0);
    o1 = cP.D[19];
    o1 = ffma2(A[0], cP.D[9],  o1);
    o1 = ffma2(A[1], cP.D[10], o1);
    o1 = ffma2(A[2], cP.D[11], o1);
    o1 = ffma2(A[3], cP.D[12], o1);
    o1 = ffma2(k,    cP.D[17], o1);
}

__device__ __forceinline__ void lsm2(float a, float b, float& ra, float& rb) {
    float m  = fmaxf(a, b);
    float mn = fminf(a, b);
    float lse = m + lg2_ap(1.0f + ex2_ap((mn - m) * LOG2E)) * LN2;
    ra = a - lse; rb = b - lse;
}

// Process one exact group of 4 samples at sample index `base`.
__device__ __forceinline__ void do_group(const float* __restrict__ x,
                                         float* __restrict__ out, int base) {
    u64 A0[16], A1[16], B0[16], B1[16];
    {
        const float4* p = (const float4*)(x + (size_t)base * 8);
        float4 a = p[0], b = p[1], c = p[2], d = p[3];
        float4 e = p[4], f = p[5], g = p[6], h = p[7];
        A0[0] = pack2(a.x, c.x); A0[1] = pack2(a.y, c.y);
        A0[2] = pack2(a.z, c.z); A0[3] = pack2(a.w, c.w);
        A0[4] = pack2(b.x, d.x); A0[5] = pack2(b.y, d.y);
        A0[6] = pack2(b.z, d.z); A0[7] = pack2(b.w, d.w);
        A1[0] = pack2(e.x, g.x); A1[1] = pack2(e.y, g.y);
        A1[2] = pack2(e.z, g.z); A1[3] = pack2(e.w, g.w);
        A1[4] = pack2(f.x, h.x); A1[5] = pack2(f.y, h.y);
        A1[6] = pack2(f.z, h.z); A1[7] = pack2(f.w, h.w);
    }

    layerfn<O_W1, O_B1, 8,  16, true >(A0, A1, B0, B1);
    layerfn<O_W2, O_B2, 16, 16, true >(B0, B1, A0, A1);
    layerfn<O_W3, O_B3, 16, 12, true >(A0, A1, B0, B1);
    layerfn<O_W4, O_B4, 12, 8,  true >(B0, B1, A0, A1);
    layerfn<O_W5, O_B5, 8,  4,  true >(A0, A1, B0, B1);
    layerfn<O_WH, O_BH, 4,  4,  false>(B0, B1, A0, A1);   // cls_out in A0/A1[0..3]

    u64 p00, p01, p10, p11;
    tail_pair(A0, p00, p01);   // samples 0,1
    tail_pair(A1, p10, p11);   // samples 2,3

    float l00a, l01a, l00b, l01b;
    unpack2(p00, l00a, l00b);
    unpack2(p01, l01a, l01b);
    float l10a, l11a, l10b, l11b;
    unpack2(p10, l10a, l10b);
    unpack2(p11, l11a, l11b);

    float r0a, r0b, r1a, r1b, r2a, r2b, r3a, r3b;
    lsm2(l00a, l01a, r0a, r0b);
    lsm2(l00b, l01b, r1a, r1b);
    lsm2(l10a, l11a, r2a, r2b);
    lsm2(l10b, l11b, r3a, r3b);

    float4* po = (float4*)(out + (size_t)base * 2);
    po[0] = make_float4(r0a, r0b, r1a, r1b);
    po[1] = make_float4(r2a, r2b, r3a, r3b);
}

// Persistent kernel: nb must be divisible by 4. 444 CTAs grid-stride over groups.
__global__ __launch_bounds__(128, 3) void qcnn_persist(
    const float* __restrict__ x, float* __restrict__ out, int ngroups)
{
    const int stride = gridDim.x * blockDim.x;
    for (int gidx = blockIdx.x * blockDim.x + threadIdx.x; gidx < ngroups; gidx += stride) {
        do_group(x, out, gidx * 4);
    }
}

// Generic fallback for arbitrary nb (one group of up-to-4 per thread, clamped).
__global__ __launch_bounds__(128, 3) void qcnn_generic(
    const float* __restrict__ x, float* __restrict__ out, int nb)
{
    int t = blockIdx.x * blockDim.x + threadIdx.x;
    int base = t * 4;
    if (base >= nb) return;
    if (base + 4 <= nb && (base & 0) == 0) {
        do_group(x, out, base);
        return;
    }
    // tail: scalar per sample
#pragma unroll 1
    for (int s = 0; s < 4 && base + s < nb; s++) {
        int idx = base + s;
        u64 A[16], B[16];
        const float4* p0 = (const float4*)(x + (size_t)idx * 8);
        float4 a = p0[0], b = p0[1];
        A[0] = pack2(a.x, a.x); A[1] = pack2(a.y, a.y);
        A[2] = pack2(a.z, a.z); A[3] = pack2(a.w, a.w);
        A[4] = pack2(b.x, b.x); A[5] = pack2(b.y, b.y);
        A[6] = pack2(b.z, b.z); A[7] = pack2(b.w, b.w);
        layerfn<O_W1, O_B1, 8,  16, true >(A, A, B, B);
        layerfn<O_W2, O_B2, 16, 16, true >(B, B, A, A);
        layerfn<O_W3, O_B3, 16, 12, true >(A, A, B, B);
        layerfn<O_W4, O_B4, 12, 8,  true >(B, B, A, A);
        layerfn<O_W5, O_B5, 8,  4,  true >(A, A, B, B);
        layerfn<O_WH, O_BH, 4,  4,  false>(B, B, A, A);
        u64 o0, o1;
        tail_pair(A, o0, o1);
        float l0, l1, dummy;
        unpack2(o0, l0, dummy);
        unpack2(o1, l1, dummy);
        float ra, rb;
        lsm2(l0, l1, ra, rb);
        out[(size_t)idx * 2]     = ra;
        out[(size_t)idx * 2 + 1] = rb;
    }
}

extern "C" void kernel_launch(void* const* d_in, const int* in_sizes, int n_in,
                              void* d_out, int out_size) {
    const float* x  = (const float*)d_in[0];
    const float* W1 = (const float*)d_in[1];
    const float* b1 = (const float*)d_in[2];
    const float* W2 = (const float*)d_in[3];
    const float* b2 = (const float*)d_in[4];
    const float* W3 = (const float*)d_in[5];
    const float* b3 = (const float*)d_in[6];
    const float* W4 = (const float*)d_in[7];
    const float* b4 = (const float*)d_in[8];
    const float* W5 = (const float*)d_in[9];
    const float* b5 = (const float*)d_in[10];
    const float* Wh = (const float*)d_in[11];
    const float* bh = (const float*)d_in[12];
    const float* Wf = (const float*)d_in[13];
    const float* bf = (const float*)d_in[14];
    const float* gm = (const float*)d_in[15];

    // 1) build duplicated weight table in device scratch
    prep_kernel<<<1, 256>>>(W1, b1, W2, b2, W3, b3, W4, b4, W5, b5,
                            Wh, bh, Wf, bf, gm);

    // 2) move into the constant bank (D2D async copy — graph-capturable)
    void* scratch_addr = nullptr;
    cudaGetSymbolAddress(&scratch_addr, gScratch);
    cudaMemcpyToSymbolAsync(cP, scratch_addr, sizeof(CParams), 0,
                            cudaMemcpyDeviceToDevice, 0);

    // 3) main kernel
    int nb = in_sizes[0] / 8;
    int threads = 128;
    if ((nb & 3) == 0) {
        int ngroups = nb / 4;
        int blocks = 148 * 3;                         // exactly one residency wave
        int needed = (ngroups + threads - 1) / threads;
        if (blocks > needed) blocks = needed;
        qcnn_persist<<<blocks, threads>>>(x, (float*)d_out, ngroups);
    } else {
        int spb = threads * 4;
        qcnn_generic<<<(nb + spb - 1) / spb, threads>>>(x, (float*)d_out, nb);
    }
}

// round 12
// speedup vs baseline: 1.2702x; 1.1668x over previous
#include <cuda_runtime.h>

typedef unsigned long long u64;
typedef unsigned int u32;

// ---------------- packed helpers (sm_10x) ----------------
__device__ __forceinline__ u64 ffma2(u64 a, u64 b, u64 c) {
    u64 d;
    asm("fma.rn.f32x2 %0, %1, %2, %3;" : "=l"(d) : "l"(a), "l"(b), "l"(c));
    return d;
}
__device__ __forceinline__ u64 mul2(u64 a, u64 b) {
    u64 d;
    asm("mul.rn.f32x2 %0, %1, %2;" : "=l"(d) : "l"(a), "l"(b));
    return d;
}
__device__ __forceinline__ u64 pack2(float lo, float hi) {
    u64 r;
    asm("mov.b64 %0, {%1, %2};" : "=l"(r) : "f"(lo), "f"(hi));
    return r;
}
__device__ __forceinline__ void unpack2(u64 v, float& lo, float& hi) {
    asm("mov.b64 {%0, %1}, %2;" : "=f"(lo), "=f"(hi) : "l"(v));
}
__device__ __forceinline__ float ex2_ap(float x) {
    float y;
    asm("ex2.approx.f32 %0, %1;" : "=f"(y) : "f"(x));
    return y;
}
__device__ __forceinline__ float lg2_ap(float x) {
    float y;
    asm("lg2.approx.f32 %0, %1;" : "=f"(y) : "f"(x));
    return y;
}
// ---- fp16x2 core (32-bit regs -> HFMA2 rt2, vs FFMA2's 3-bank rt3) ----
__device__ __forceinline__ u32 hfma2(u32 a, u32 b, u32 c) {
    u32 d;
    asm("fma.rn.f16x2 %0, %1, %2, %3;" : "=r"(d) : "r"(a), "r"(b), "r"(c));
    return d;
}
__device__ __forceinline__ u32 tanh_h2(u32 v) {
    u32 d;
    asm("tanh.approx.f16x2 %0, %1;" : "=r"(d) : "r"(v));
    return d;
}
// pack two f32 (lo, hi) into f16x2; ordering validated in R10.
__device__ __forceinline__ u32 pack_h2(float lo, float hi) {
    u32 d;
    asm("cvt.rn.f16x2.f32 %0, %1, %2;" : "=r"(d) : "f"(hi), "f"(lo));
    return d;
}
__device__ __forceinline__ u64 h2_to_f32x2(u32 v) {
    u64 d;
    asm("{\n\t.reg .b16 l, h;\n\t.reg .f32 flo, fhi;\n\tmov.b32 {l, h}, %1;\n\t"
        "cvt.f32.f16 flo, l;\n\tcvt.f32.f16 fhi, h;\n\tmov.b64 %0, {flo, fhi};\n\t}"
        : "=l"(d) : "r"(v));
    return d;
}

// ---------------- constant tables ----------------
// H[]: ALL layer weights/biases as f16x2 duplicated (w,w), u32.
// D[]: f32x2 tail constants. Scalar compile-time indices only -> LDCU.
enum {
    O_W1 = 0,           // 16x8  = 128
    O_B1 = 128,         // 16
    O_W2 = 144,         // 16x16 = 256
    O_B2 = 400,         // 16
    O_W3 = 416,         // 12x16 = 192
    O_B3 = 608,         // 12
    O_W4 = 620,         // 8x12  = 96
    O_B4 = 716,         // 8
    O_W5 = 724,         // 4x8   = 32
    O_B5 = 756,         // 4
    O_WH = 760,         // 4x4   = 16
    O_BH = 776,         // 4
    W_TOTAL = 780
};
enum { D_TOTAL = 21 };  // D[0..17]=Wf dup, D[18]=bf0, D[19]=bf1, D[20]=-gamma*log2e

struct CParams {
    u32 H[W_TOTAL];
    u64 D[D_TOTAL];
    u32 pad;
};

__constant__ CParams cP;
__device__ CParams gScratch;

#define LOG2E 1.4426950408889634f
#define LN2   0.6931471805599453f

// ---------------- prep kernel ----------------
__global__ void prep_kernel(
    const float* __restrict__ W1, const float* __restrict__ b1,
    const float* __restrict__ W2, const float* __restrict__ b2,
    const float* __restrict__ W3, const float* __restrict__ b3,
    const float* __restrict__ W4, const float* __restrict__ b4,
    const float* __restrict__ W5, const float* __restrict__ b5,
    const float* __restrict__ Wh, const float* __restrict__ bh,
    const float* __restrict__ Wf, const float* __restrict__ bf,
    const float* __restrict__ gamma)
{
    int tid = threadIdx.x;
#define CP_(off, src, n)                                            \
    for (int i = tid; i < (n); i += blockDim.x) {                   \
        float f = (src)[i];                                         \
        u32 h;                                                      \
        asm("cvt.rn.f16x2.f32 %0, %1, %1;" : "=r"(h) : "f"(f));     \
        gScratch.H[(off) + i] = h;                                  \
    }
    CP_(O_W1, W1, 128); CP_(O_B1, b1, 16);
    CP_(O_W2, W2, 256); CP_(O_B2, b2, 16);
    CP_(O_W3, W3, 192); CP_(O_B3, b3, 12);
    CP_(O_W4, W4, 96);  CP_(O_B4, b4, 8);
    CP_(O_W5, W5, 32);  CP_(O_B5, b5, 4);
    CP_(O_WH, Wh, 16);  CP_(O_BH, bh, 4);
#undef CP_
    if (tid < 18) { float f = Wf[tid]; gScratch.D[tid] = pack2(f, f); }
    if (tid == 18) { float f = bf[0]; gScratch.D[18] = pack2(f, f); }
    if (tid == 19) { float f = bf[1]; gScratch.D[19] = pack2(f, f); }
    if (tid == 20) { float f = -gamma[0] * LOG2E; gScratch.D[20] = pack2(f, f); }
}

// ---------------- fp16x2 dense layer on TWO packed pairs (4 samples) ----------------
// Each weight LDCU feeds two HFMA2s. No pack/unpack movs anywhere in the layer.
template <int OFF_W, int OFF_B, int IN, int OUT, bool ACT>
__device__ __forceinline__ void layer_h(const u32* __restrict__ in0, const u32* __restrict__ in1,
                                        u32* __restrict__ out0, u32* __restrict__ out1) {
#pragma unroll
    for (int j = 0; j < OUT; j++) {
        u32 a0 = cP.H[OFF_B + j];
        u32 a1 = a0;
#pragma unroll
        for (int i = 0; i < IN; i++) {
            u32 w = cP.H[OFF_W + j * IN + i];
            a0 = hfma2(in0[i], w, a0);
            a1 = hfma2(in1[i], w, a1);
        }
        if (ACT) { a0 = tanh_h2(a0); a1 = tanh_h2(a1); }
        out0[j] = a0;
        out1[j] = a1;
    }
}

// ---- f32 tail (exactly the R9 path) ----
__device__ __forceinline__ void tail_pair(const u64* __restrict__ A, u64& o0, u64& o1) {
    u64 s2 = mul2(A[0], A[0]);
    s2 = ffma2(A[1], A[1], s2);
    s2 = ffma2(A[2], A[2], s2);
    s2 = ffma2(A[3], A[3], s2);
    u64 g = mul2(s2, cP.D[20]);
    float glo, ghi;
    unpack2(g, glo, ghi);
    u64 k = pack2(ex2_ap(glo), ex2_ap(ghi));
    o0 = cP.D[18];
    o0 = ffma2(A[0], cP.D[0], o0);
    o0 = ffma2(A[1], cP.D[1], o0);
    o0 = ffma2(A[2], cP.D[2], o0);
    o0 = ffma2(A[3], cP.D[3], o0);
    o0 = ffma2(k,    cP.D[8], o0);
    o1 = cP.D[19];
    o1 = ffma2(A[0], cP.D[9],  o1);
    o1 = ffma2(A[1], cP.D[10], o1);
    o1 = ffma2(A[2], cP.D[11], o1);
    o1 = ffma2(A[3], cP.D[12], o1);
    o1 = ffma2(k,    cP.D[17], o1);
}

__device__ __forceinline__ void lsm2(float a, float b, float& ra, float& rb) {
    float m  = fmaxf(a, b);
    float mn = fminf(a, b);
    float lse = m + lg2_ap(1.0f + ex2_ap((mn - m) * LOG2E)) * LN2;
    ra = a - lse; rb = b - lse;
}

template <bool EXACT>
__global__ __launch_bounds__(128, 4) void qcnn_kernel(
    const float* __restrict__ x, float* __restrict__ out, int nb)
{
    int t = blockIdx.x * blockDim.x + threadIdx.x;
    int base = t * 4;
    if (!EXACT && base >= nb) return;

    // ---- load 4 samples, convert once to f16x2 (sample-pairs in lo/hi) ----
    u32 H0[16], H1[16], G0[16], G1[16];
    {
        const float4* p0 = (const float4*)(x + (size_t)base * 8);
        float4 a, b, c, d, e, f, g, h;
        if (EXACT) {
            a = p0[0]; b = p0[1]; c = p0[2]; d = p0[3];
            e = p0[4]; f = p0[5]; g = p0[6]; h = p0[7];
        } else {
            int s1 = (base + 1 < nb) ? base + 1 : nb - 1;
            int s2 = (base + 2 < nb) ? base + 2 : nb - 1;
            int s3 = (base + 3 < nb) ? base + 3 : nb - 1;
            const float4* p1 = (const float4*)(x + (size_t)s1 * 8);
            const float4* p2 = (const float4*)(x + (size_t)s2 * 8);
            const float4* p3 = (const float4*)(x + (size_t)s3 * 8);
            a = p0[0]; b = p0[1];
            c = p1[0]; d = p1[1];
            e = p2[0]; f = p2[1];
            g = p3[0]; h = p3[1];
        }
        H0[0] = pack_h2(a.x, c.x); H0[1] = pack_h2(a.y, c.y);
        H0[2] = pack_h2(a.z, c.z); H0[3] = pack_h2(a.w, c.w);
        H0[4] = pack_h2(b.x, d.x); H0[5] = pack_h2(b.y, d.y);
        H0[6] = pack_h2(b.z, d.z); H0[7] = pack_h2(b.w, d.w);
        H1[0] = pack_h2(e.x, g.x); H1[1] = pack_h2(e.y, g.y);
        H1[2] = pack_h2(e.z, g.z); H1[3] = pack_h2(e.w, g.w);
        H1[4] = pack_h2(f.x, h.x); H1[5] = pack_h2(f.y, h.y);
        H1[6] = pack_h2(f.z, h.z); H1[7] = pack_h2(f.w, h.w);
    }

    layer_h<O_W1, O_B1, 8,  16, true >(H0, H1, G0, G1);
    layer_h<O_W2, O_B2, 16, 16, true >(G0, G1, H0, H1);
    layer_h<O_W3, O_B3, 16, 12, true >(H0, H1, G0, G1);
    layer_h<O_W4, O_B4, 12, 8,  true >(G0, G1, H0, H1);
    layer_h<O_W5, O_B5, 8,  4,  true >(H0, H1, G0, G1);
    layer_h<O_WH, O_BH, 4,  4,  false>(G0, G1, H0, H1);   // cls_out (h2) in H0/H1[0..3]

    // ---- convert cls_out to f32x2 and run the f32 tail ----
    u64 A0[4], A1[4];
#pragma unroll
    for (int j = 0; j < 4; j++) {
        A0[j] = h2_to_f32x2(H0[j]);
        A1[j] = h2_to_f32x2(H1[j]);
    }

    u64 p00, p01, p10, p11;
    tail_pair(A0, p00, p01);   // samples 0,1
    tail_pair(A1, p10, p11);   // samples 2,3

    float l00a, l01a, l00b, l01b;
    unpack2(p00, l00a, l00b);
    unpack2(p01, l01a, l01b);
    float l10a, l11a, l10b, l11b;
    unpack2(p10, l10a, l10b);
    unpack2(p11, l11a, l11b);

    float r0a, r0b, r1a, r1b, r2a, r2b, r3a, r3b;
    lsm2(l00a, l01a, r0a, r0b);    // sample 0
    lsm2(l00b, l01b, r1a, r1b);    // sample 1
    lsm2(l10a, l11a, r2a, r2b);    // sample 2
    lsm2(l10b, l11b, r3a, r3b);    // sample 3

    if (EXACT || base + 4 <= nb) {
        float4* po = (float4*)(out + (size_t)base * 2);
        po[0] = make_float4(r0a, r0b, r1a, r1b);
        po[1] = make_float4(r2a, r2b, r3a, r3b);
    } else {
        float rs[4][2] = {{r0a, r0b}, {r1a, r1b}, {r2a, r2b}, {r3a, r3b}};
#pragma unroll
        for (int s = 0; s < 4; s++) {
            if (base + s < nb) {
                out[(base + s) * 2 + 0] = rs[s][0];
                out[(base + s) * 2 + 1] = rs[s][1];
            }
        }
    }
}

extern "C" void kernel_launch(void* const* d_in, const int* in_sizes, int n_in,
                              void* d_out, int out_size) {
    const float* x  = (const float*)d_in[0];
    const float* W1 = (const float*)d_in[1];
    const float* b1 = (const float*)d_in[2];
    const float* W2 = (const float*)d_in[3];
    const float* b2 = (const float*)d_in[4];
    const float* W3 = (const float*)d_in[5];
    const float* b3 = (const float*)d_in[6];
    const float* W4 = (const float*)d_in[7];
    const float* b4 = (const float*)d_in[8];
    const float* W5 = (const float*)d_in[9];
    const float* b5 = (const float*)d_in[10];
    const float* Wh = (const float*)d_in[11];
    const float* bh = (const float*)d_in[12];
    const float* Wf = (const float*)d_in[13];
    const float* bf = (const float*)d_in[14];
    const float* gm = (const float*)d_in[15];

    // 1) build fp16x2 weight table in device scratch
    prep_kernel<<<1, 256>>>(W1, b1, W2, b2, W3, b3, W4, b4, W5, b5,
                            Wh, bh, Wf, bf, gm);

    // 2) move into the constant bank (D2D async copy — graph-capturable)
    void* scratch_addr = nullptr;
    cudaGetSymbolAddress(&scratch_addr, gScratch);
    cudaMemcpyToSymbolAsync(cP, scratch_addr, sizeof(CParams), 0,
                            cudaMemcpyDeviceToDevice, 0);

    // 3) main kernel — exact-grid specialization when nb divides evenly
    int nb = in_sizes[0] / 8;
    int threads = 128;
    int spb = threads * 4;
    if (nb % spb == 0) {
        qcnn_kernel<true><<<nb / spb, threads>>>(x, (float*)d_out, nb);
    } else {
        qcnn_kernel<false><<<(nb + spb - 1) / spb, threads>>>(x, (float*)d_out, nb);
    }
}